// round 15
// baseline (speedup 1.0000x reference)
#include <cuda_runtime.h>
#include <cuda_bf16.h>

// MaskCNN1: out[b,c,h,w] = (w < floor(W * percents[b])) ? x[b,c,h,w] : 0
// x [16, 64, 80, 1024] fp32, percents [16] fp32.
//
// FINAL. Roofline-bound at the write-dominated HBM stream ceiling
// (~5.85 TB/s on this part; verified across MLP 1/4/8, 128/256-bit accesses,
// all L2 policies incl. wt, and phase-separated pure-write streams).
// Traffic is minimal: 335 MB mandatory writes + ~69 MB reads (masked region
// never loads). Config: float4, x4 unroll with stride W4=256 so the W-column
// (and mask predicate) is unroll-invariant -> one branch per thread,
// 4 front-batched LDG.128 + 4 STG.128. Loads ld.global.nc + L2::evict_last,
// stores L2::evict_first.

using u64 = unsigned long long;

static constexpr int B = 16;
static constexpr int C = 64;
static constexpr int H = 80;
static constexpr int W = 1024;
static constexpr int W4 = W / 4;               // 256 float4 per row
static constexpr int PER_B4 = C * H * W4;      // 1,310,720 float4 per batch
static constexpr int UNROLL = 4;
static constexpr int BLOCK = 256;
static constexpr int PER_BLOCK = BLOCK * UNROLL;   // 1024 float4 (4 rows)

__device__ __forceinline__ float4 ld_hint(const float4* p, u64 pol) {
    float4 v;
    asm volatile("ld.global.nc.L2::cache_hint.v4.f32 {%0,%1,%2,%3}, [%4], %5;"
                 : "=f"(v.x), "=f"(v.y), "=f"(v.z), "=f"(v.w)
                 : "l"(p), "l"(pol));
    return v;
}
__device__ __forceinline__ void st_hint(float4* p, float4 v, u64 pol) {
    asm volatile("st.global.L2::cache_hint.v4.f32 [%0], {%1,%2,%3,%4}, %5;"
                 :: "l"(p), "f"(v.x), "f"(v.y), "f"(v.z), "f"(v.w), "l"(pol)
                 : "memory");
}

__global__ __launch_bounds__(BLOCK)
void mask_cnn_kernel(const float4* __restrict__ x,
                     const float* __restrict__ percents,
                     float4* __restrict__ out) {
    const int b   = blockIdx.y;
    const int tid = threadIdx.x;

    // L2 policies: created once per thread (cheap fixed-lat ops).
    u64 pol_last, pol_first;
    asm volatile("createpolicy.fractional.L2::evict_last.b64 %0, 1.0;"  : "=l"(pol_last));
    asm volatile("createpolicy.fractional.L2::evict_first.b64 %0, 1.0;" : "=l"(pol_first));

    const float p = __ldg(&percents[b]);
    const int len = (int)((float)W * p);     // floor via int truncation (p >= 0)

    // Column == tid across the unroll (stride W4=256; block base % 256 == 0),
    // so the mask predicate is unroll-invariant.
    const int pos = tid << 2;

    const long base = (long)b * PER_B4 + (long)blockIdx.x * PER_BLOCK + tid;

    if (pos + 3 < len) {
        // fully valid: 4 front-batched loads (evict_last), 4 stores (evict_first)
        float4 v[UNROLL];
        #pragma unroll
        for (int i = 0; i < UNROLL; i++) v[i] = ld_hint(&x[base + i * W4], pol_last);
        #pragma unroll
        for (int i = 0; i < UNROLL; i++) st_hint(&out[base + i * W4], v[i], pol_first);
    } else if (pos >= len) {
        // fully masked: write zeros, never read x
        const float4 z = make_float4(0.f, 0.f, 0.f, 0.f);
        #pragma unroll
        for (int i = 0; i < UNROLL; i++) st_hint(&out[base + i * W4], z, pol_first);
    } else {
        // straddling float4 (one column of 256): per-lane select
        const bool k0 = pos + 0 < len, k1 = pos + 1 < len,
                   k2 = pos + 2 < len, k3 = pos + 3 < len;
        float4 v[UNROLL];
        #pragma unroll
        for (int i = 0; i < UNROLL; i++) v[i] = ld_hint(&x[base + i * W4], pol_last);
        #pragma unroll
        for (int i = 0; i < UNROLL; i++) {
            v[i].x = k0 ? v[i].x : 0.f;
            v[i].y = k1 ? v[i].y : 0.f;
            v[i].z = k2 ? v[i].z : 0.f;
            v[i].w = k3 ? v[i].w : 0.f;
        }
        #pragma unroll
        for (int i = 0; i < UNROLL; i++) st_hint(&out[base + i * W4], v[i], pol_first);
    }
}

extern "C" void kernel_launch(void* const* d_in, const int* in_sizes, int n_in,
                              void* d_out, int out_size) {
    const float4* x        = (const float4*)d_in[0];
    const float*  percents = (const float*)d_in[1];
    float4*       out      = (float4*)d_out;

    dim3 grid(PER_B4 / PER_BLOCK, B, 1);   // 1280 x 16 blocks
    mask_cnn_kernel<<<grid, BLOCK>>>(x, percents, out);
}

// round 16
// speedup vs baseline: 1.0061x; 1.0061x over previous
#include <cuda_runtime.h>
#include <cuda_bf16.h>

// MaskCNN1: out[b,c,h,w] = (w < floor(W * percents[b])) ? x[b,c,h,w] : 0
// x [16, 64, 80, 1024] fp32, percents [16] fp32.
//
// FINAL family (roofline-bound at the write-dominated HBM stream ceiling,
// ~5.8 TB/s; traffic minimal: 335 MB mandatory writes + ~69 MB reads, masked
// region never loads). R16 adds the .L2::256B fetch-granularity qualifier to
// the x loads: warp loads are 4KB-contiguous so 256B sectors are fully used;
// halves the DRAM read-command count interleaved into the write stream.
// Everything else identical to the confirmed-best config: float4, x4 unroll
// with unroll-invariant predicate, evict_last loads, evict_first stores.

using u64 = unsigned long long;

static constexpr int B = 16;
static constexpr int C = 64;
static constexpr int H = 80;
static constexpr int W = 1024;
static constexpr int W4 = W / 4;               // 256 float4 per row
static constexpr int PER_B4 = C * H * W4;      // 1,310,720 float4 per batch
static constexpr int UNROLL = 4;
static constexpr int BLOCK = 256;
static constexpr int PER_BLOCK = BLOCK * UNROLL;   // 1024 float4 (4 rows)

__device__ __forceinline__ float4 ld_hint(const float4* p, u64 pol) {
    float4 v;
    asm volatile("ld.global.nc.L2::cache_hint.L2::256B.v4.f32 {%0,%1,%2,%3}, [%4], %5;"
                 : "=f"(v.x), "=f"(v.y), "=f"(v.z), "=f"(v.w)
                 : "l"(p), "l"(pol));
    return v;
}
__device__ __forceinline__ void st_hint(float4* p, float4 v, u64 pol) {
    asm volatile("st.global.L2::cache_hint.v4.f32 [%0], {%1,%2,%3,%4}, %5;"
                 :: "l"(p), "f"(v.x), "f"(v.y), "f"(v.z), "f"(v.w), "l"(pol)
                 : "memory");
}

__global__ __launch_bounds__(BLOCK)
void mask_cnn_kernel(const float4* __restrict__ x,
                     const float* __restrict__ percents,
                     float4* __restrict__ out) {
    const int b   = blockIdx.y;
    const int tid = threadIdx.x;

    // L2 policies: created once per thread (cheap fixed-lat ops).
    u64 pol_last, pol_first;
    asm volatile("createpolicy.fractional.L2::evict_last.b64 %0, 1.0;"  : "=l"(pol_last));
    asm volatile("createpolicy.fractional.L2::evict_first.b64 %0, 1.0;" : "=l"(pol_first));

    const float p = __ldg(&percents[b]);
    const int len = (int)((float)W * p);     // floor via int truncation (p >= 0)

    // Column == tid across the unroll (stride W4=256; block base % 256 == 0),
    // so the mask predicate is unroll-invariant.
    const int pos = tid << 2;

    const long base = (long)b * PER_B4 + (long)blockIdx.x * PER_BLOCK + tid;

    if (pos + 3 < len) {
        // fully valid: 4 front-batched loads (evict_last, 256B fetch), 4 stores
        float4 v[UNROLL];
        #pragma unroll
        for (int i = 0; i < UNROLL; i++) v[i] = ld_hint(&x[base + i * W4], pol_last);
        #pragma unroll
        for (int i = 0; i < UNROLL; i++) st_hint(&out[base + i * W4], v[i], pol_first);
    } else if (pos >= len) {
        // fully masked: write zeros, never read x
        const float4 z = make_float4(0.f, 0.f, 0.f, 0.f);
        #pragma unroll
        for (int i = 0; i < UNROLL; i++) st_hint(&out[base + i * W4], z, pol_first);
    } else {
        // straddling float4 (one column of 256): per-lane select
        const bool k0 = pos + 0 < len, k1 = pos + 1 < len,
                   k2 = pos + 2 < len, k3 = pos + 3 < len;
        float4 v[UNROLL];
        #pragma unroll
        for (int i = 0; i < UNROLL; i++) v[i] = ld_hint(&x[base + i * W4], pol_last);
        #pragma unroll
        for (int i = 0; i < UNROLL; i++) {
            v[i].x = k0 ? v[i].x : 0.f;
            v[i].y = k1 ? v[i].y : 0.f;
            v[i].z = k2 ? v[i].z : 0.f;
            v[i].w = k3 ? v[i].w : 0.f;
        }
        #pragma unroll
        for (int i = 0; i < UNROLL; i++) st_hint(&out[base + i * W4], v[i], pol_first);
    }
}

extern "C" void kernel_launch(void* const* d_in, const int* in_sizes, int n_in,
                              void* d_out, int out_size) {
    const float4* x        = (const float4*)d_in[0];
    const float*  percents = (const float*)d_in[1];
    float4*       out      = (float4*)d_out;

    dim3 grid(PER_B4 / PER_BLOCK, B, 1);   // 1280 x 16 blocks
    mask_cnn_kernel<<<grid, BLOCK>>>(x, percents, out);
}